// round 2
// baseline (speedup 1.0000x reference)
#include <cuda_runtime.h>
#include <cuda_bf16.h>

// PointLayerNorm: segment-wise layernorm over (batch, segment) groups.
// x: [B, N, C] fp32; batch_offsets: [S+1] int32; batch_indices: [N] int32
// (JAX x64-disabled downcasts the reference's int64 arrays to int32);
// weight, bias: [C] fp32. Output [B, N, C] fp32.
//
// var = E[x^2] - mean^2  -> single reduction pass (sum, sumsq).
// Traffic floor: read x twice + write once ~= 921 MB -> HBM bound.

#define Bc 4
#define Nc 200000
#define Cc 96
#define Sc 32
#define KEYS (Bc * Sc)
#define EPSF 1e-5f

__device__ float g_sum[KEYS];
__device__ float g_sumsq[KEYS];
__device__ float g_mean[KEYS];
__device__ float g_inv[KEYS];

__global__ void pln_zero_kernel() {
    int i = threadIdx.x;
    if (i < KEYS) { g_sum[i] = 0.f; g_sumsq[i] = 0.f; }
}

// One warp processes a contiguous chunk of points; key (b*S + seg) changes
// rarely (avg segment ~6250 points), so we accumulate in registers and flush
// via warp-reduce + 2 atomics only on key change.
__global__ __launch_bounds__(256) void pln_reduce_kernel(
    const float* __restrict__ x, const int* __restrict__ idx)
{
    const int P = Bc * Nc;
    int wid    = (blockIdx.x * blockDim.x + threadIdx.x) >> 5;
    int lane   = threadIdx.x & 31;
    int totalW = (gridDim.x * blockDim.x) >> 5;
    int chunk  = (P + totalW - 1) / totalW;
    int g0 = wid * chunk;
    int g1 = g0 + chunk; if (g1 > P) g1 = P;

    float s = 0.f, s2 = 0.f;
    int curKey = -1;

    for (int g = g0; g < g1; ++g) {
        int b = g / Nc;
        int n = g - b * Nc;
        int key = (b * Sc + __ldg(&idx[n])) & (KEYS - 1);
        if (key != curKey) {
            if (curKey >= 0) {
                #pragma unroll
                for (int o = 16; o; o >>= 1) {
                    s  += __shfl_xor_sync(0xffffffffu, s,  o);
                    s2 += __shfl_xor_sync(0xffffffffu, s2, o);
                }
                if (lane == 0) {
                    atomicAdd(&g_sum[curKey],   s);
                    atomicAdd(&g_sumsq[curKey], s2);
                }
                s = 0.f; s2 = 0.f;
            }
            curKey = key;
        }
        const float* p = x + (size_t)g * Cc;
        float v0 = __ldg(p + lane);
        float v1 = __ldg(p + lane + 32);
        float v2 = __ldg(p + lane + 64);
        s  += v0 + v1 + v2;
        s2 = fmaf(v0, v0, fmaf(v1, v1, fmaf(v2, v2, s2)));
    }
    if (curKey >= 0) {
        #pragma unroll
        for (int o = 16; o; o >>= 1) {
            s  += __shfl_xor_sync(0xffffffffu, s,  o);
            s2 += __shfl_xor_sync(0xffffffffu, s2, o);
        }
        if (lane == 0) {
            atomicAdd(&g_sum[curKey],   s);
            atomicAdd(&g_sumsq[curKey], s2);
        }
    }
}

__global__ void pln_finalize_kernel(const int* __restrict__ offs) {
    int k = threadIdx.x;
    if (k < KEYS) {
        int seg = k & (Sc - 1);
        float cnt = (float)(offs[seg + 1] - offs[seg]) * (float)Cc;
        float m   = g_sum[k] / cnt;
        float var = g_sumsq[k] / cnt - m * m;
        g_mean[k] = m;
        g_inv[k]  = rsqrtf(var + EPSF);
    }
}

__global__ __launch_bounds__(256) void pln_norm_kernel(
    const float* __restrict__ x, const int* __restrict__ idx,
    const float* __restrict__ w, const float* __restrict__ bias,
    float* __restrict__ out)
{
    const int P = Bc * Nc;
    int wid    = (blockIdx.x * blockDim.x + threadIdx.x) >> 5;
    int lane   = threadIdx.x & 31;
    int totalW = (gridDim.x * blockDim.x) >> 5;
    int chunk  = (P + totalW - 1) / totalW;
    int g0 = wid * chunk;
    int g1 = g0 + chunk; if (g1 > P) g1 = P;
    if (g0 >= g1) return;

    // This lane always handles channels lane, lane+32, lane+64.
    float w0 = __ldg(w + lane),      w1 = __ldg(w + lane + 32),      w2 = __ldg(w + lane + 64);
    float a0 = __ldg(bias + lane),   a1 = __ldg(bias + lane + 32),   a2 = __ldg(bias + lane + 64);

    int curKey = -1;
    float sc0 = 0.f, sc1 = 0.f, sc2 = 0.f, sh0 = 0.f, sh1 = 0.f, sh2 = 0.f;

    for (int g = g0; g < g1; ++g) {
        int b = g / Nc;
        int n = g - b * Nc;
        int key = (b * Sc + __ldg(&idx[n])) & (KEYS - 1);
        if (key != curKey) {
            curKey = key;
            float m  = g_mean[key];
            float iv = g_inv[key];
            sc0 = iv * w0; sh0 = fmaf(-m, sc0, a0);
            sc1 = iv * w1; sh1 = fmaf(-m, sc1, a1);
            sc2 = iv * w2; sh2 = fmaf(-m, sc2, a2);
        }
        const float* p = x   + (size_t)g * Cc;
        float*       q = out + (size_t)g * Cc;
        q[lane]      = fmaf(__ldg(p + lane),      sc0, sh0);
        q[lane + 32] = fmaf(__ldg(p + lane + 32), sc1, sh1);
        q[lane + 64] = fmaf(__ldg(p + lane + 64), sc2, sh2);
    }
}

extern "C" void kernel_launch(void* const* d_in, const int* in_sizes, int n_in,
                              void* d_out, int out_size) {
    const float* x    = (const float*)d_in[0];
    const int*   offs = (const int*)d_in[1];
    const int*   idx  = (const int*)d_in[2];
    const float* w    = (const float*)d_in[3];
    const float* bias = (const float*)d_in[4];
    float* out = (float*)d_out;

    pln_zero_kernel<<<1, 128>>>();
    pln_reduce_kernel<<<2048, 256>>>(x, idx);
    pln_finalize_kernel<<<1, 128>>>(offs);
    pln_norm_kernel<<<2048, 256>>>(x, idx, w, bias, out);
}

// round 3
// speedup vs baseline: 1.0452x; 1.0452x over previous
#include <cuda_runtime.h>
#include <cuda_bf16.h>

// PointLayerNorm: segment-wise layernorm over (batch, segment) groups.
// x: [B, N, C] fp32; batch_offsets: [S+1] int32; batch_indices: [N] int32;
// weight, bias: [C] fp32. Output [B, N, C] fp32.
//
// R3: vectorized float4 memory access everywhere. Reduce = warp-per-chunk,
// 24 lanes x float4 per point row. Norm = element-parallel float4 grid-stride.

#define Bc 4
#define Nc 200000
#define Cc 96
#define C4 (Cc / 4)            // 24 float4 per point
#define Sc 32
#define KEYS (Bc * Sc)
#define EPSF 1e-5f

__device__ float g_sum[KEYS];
__device__ float g_sumsq[KEYS];
__device__ float g_mean[KEYS];
__device__ float g_inv[KEYS];

__global__ void pln_zero_kernel() {
    int i = threadIdx.x;
    if (i < KEYS) { g_sum[i] = 0.f; g_sumsq[i] = 0.f; }
}

// One warp owns a contiguous chunk of points. Lanes 0..23 each load one
// float4 of the 96-float row; per-lane running (sum, sumsq) flushed via
// full-warp shuffle-reduce + 2 atomics on key change (rare: ~127 boundaries).
__global__ __launch_bounds__(256) void pln_reduce_kernel(
    const float4* __restrict__ x4, const int* __restrict__ idx)
{
    const int P = Bc * Nc;
    int wid    = (blockIdx.x * blockDim.x + threadIdx.x) >> 5;
    int lane   = threadIdx.x & 31;
    int totalW = (gridDim.x * blockDim.x) >> 5;
    int chunk  = (P + totalW - 1) / totalW;
    int g0 = wid * chunk;
    int g1 = g0 + chunk; if (g1 > P) g1 = P;

    float s = 0.f, s2 = 0.f;
    int curKey = -1;
    bool act = lane < C4;

    for (int g = g0; g < g1; ++g) {
        int b = g / Nc;
        int n = g - b * Nc;
        int key = (b * Sc + __ldg(&idx[n])) & (KEYS - 1);
        if (key != curKey) {
            if (curKey >= 0) {
                #pragma unroll
                for (int o = 16; o; o >>= 1) {
                    s  += __shfl_xor_sync(0xffffffffu, s,  o);
                    s2 += __shfl_xor_sync(0xffffffffu, s2, o);
                }
                if (lane == 0) {
                    atomicAdd(&g_sum[curKey],   s);
                    atomicAdd(&g_sumsq[curKey], s2);
                }
                s = 0.f; s2 = 0.f;
            }
            curKey = key;
        }
        if (act) {
            float4 v = __ldg(x4 + (size_t)g * C4 + lane);
            s  += (v.x + v.y) + (v.z + v.w);
            s2  = fmaf(v.x, v.x, s2);
            s2  = fmaf(v.y, v.y, s2);
            s2  = fmaf(v.z, v.z, s2);
            s2  = fmaf(v.w, v.w, s2);
        }
    }
    if (curKey >= 0) {
        #pragma unroll
        for (int o = 16; o; o >>= 1) {
            s  += __shfl_xor_sync(0xffffffffu, s,  o);
            s2 += __shfl_xor_sync(0xffffffffu, s2, o);
        }
        if (lane == 0) {
            atomicAdd(&g_sum[curKey],   s);
            atomicAdd(&g_sumsq[curKey], s2);
        }
    }
}

__global__ void pln_finalize_kernel(const int* __restrict__ offs) {
    int k = threadIdx.x;
    if (k < KEYS) {
        int seg = k & (Sc - 1);
        float cnt = (float)(offs[seg + 1] - offs[seg]) * (float)Cc;
        float m   = g_sum[k] / cnt;
        float var = g_sumsq[k] / cnt - m * m;
        g_mean[k] = m;
        g_inv[k]  = rsqrtf(var + EPSF);
    }
}

// Element-parallel over float4s: 1 LDG.128 + 1 STG.128 per element; idx /
// mean / inv / weight / bias all L1-resident. No key-change tracking needed.
__global__ __launch_bounds__(256) void pln_norm_kernel(
    const float4* __restrict__ x4, const int* __restrict__ idx,
    const float4* __restrict__ w4, const float4* __restrict__ b4,
    float4* __restrict__ out4)
{
    const int P = Bc * Nc;
    const long long E = (long long)P * C4;   // 19.2M float4s
    long long stride = (long long)gridDim.x * blockDim.x;

    for (long long e = (long long)blockIdx.x * blockDim.x + threadIdx.x;
         e < E; e += stride) {
        int p  = (int)(e / C4);
        int c4 = (int)(e - (long long)p * C4);
        int b  = p / Nc;
        int n  = p - b * Nc;
        int key = (b * Sc + __ldg(&idx[n])) & (KEYS - 1);

        float m  = g_mean[key];
        float iv = g_inv[key];
        float4 wv = __ldg(w4 + c4);
        float4 bv = __ldg(b4 + c4);
        float4 xv = __ldg(x4 + e);

        float sc, sh;
        float4 o;
        sc = iv * wv.x; sh = fmaf(-m, sc, bv.x); o.x = fmaf(xv.x, sc, sh);
        sc = iv * wv.y; sh = fmaf(-m, sc, bv.y); o.y = fmaf(xv.y, sc, sh);
        sc = iv * wv.z; sh = fmaf(-m, sc, bv.z); o.z = fmaf(xv.z, sc, sh);
        sc = iv * wv.w; sh = fmaf(-m, sc, bv.w); o.w = fmaf(xv.w, sc, sh);
        out4[e] = o;
    }
}

extern "C" void kernel_launch(void* const* d_in, const int* in_sizes, int n_in,
                              void* d_out, int out_size) {
    const float4* x4   = (const float4*)d_in[0];
    const int*    offs = (const int*)d_in[1];
    const int*    idx  = (const int*)d_in[2];
    const float4* w4   = (const float4*)d_in[3];
    const float4* b4   = (const float4*)d_in[4];
    float4* out4 = (float4*)d_out;

    pln_zero_kernel<<<1, 128>>>();
    pln_reduce_kernel<<<2048, 256>>>(x4, idx);
    pln_finalize_kernel<<<1, 128>>>(offs);
    pln_norm_kernel<<<2048, 256>>>(x4, idx, w4, b4, out4);
}

// round 4
// speedup vs baseline: 1.2744x; 1.2192x over previous
#include <cuda_runtime.h>
#include <cuda_bf16.h>

// PointLayerNorm, R4: division-free norm loop + per-(key,channel) scale/shift
// tables + full-warp 4-point-group reduce.

#define Bc 4
#define Nc 200000
#define Cc 96
#define C4 (Cc / 4)            // 24 float4 per point
#define Sc 32
#define KEYS (Bc * Sc)
#define EPSF 1e-5f

__device__ float g_sum[KEYS];
__device__ float g_sumsq[KEYS];
__device__ float4 g_sc[KEYS * C4];   // per (key, c4) scale
__device__ float4 g_sh[KEYS * C4];   // per (key, c4) shift

__global__ void pln_zero_kernel() {
    int i = threadIdx.x;
    if (i < KEYS) { g_sum[i] = 0.f; g_sumsq[i] = 0.f; }
}

__device__ __forceinline__ void flush_key(int key, float& s, float& s2, int lane) {
    #pragma unroll
    for (int o = 16; o; o >>= 1) {
        s  += __shfl_xor_sync(0xffffffffu, s,  o);
        s2 += __shfl_xor_sync(0xffffffffu, s2, o);
    }
    if (lane == 0) {
        atomicAdd(&g_sum[key],   s);
        atomicAdd(&g_sumsq[key], s2);
    }
    s = 0.f; s2 = 0.f;
}

// One warp owns a contiguous chunk (multiple of 4 points). Fast path: the 4
// points of a group share one key (true except at ~127 segment boundaries);
// all 32 lanes read 3 float4s covering the group's 96 consecutive float4s.
__global__ __launch_bounds__(256) void pln_reduce_kernel(
    const float4* __restrict__ x4, const int* __restrict__ idx)
{
    const int P = Bc * Nc;                       // 800000, multiple of 4
    int wid    = (blockIdx.x * blockDim.x + threadIdx.x) >> 5;
    int lane   = threadIdx.x & 31;
    int totalW = (gridDim.x * blockDim.x) >> 5;
    int chunk  = (((P + totalW - 1) / totalW) + 3) & ~3;
    int g0 = wid * chunk;
    int g1 = g0 + chunk; if (g1 > P) g1 = P;

    float s = 0.f, s2 = 0.f;
    int curKey = -1;

    for (int g = g0; g < g1; g += 4) {
        int kl = 0;
        if (lane < 4) {
            int gi = g + lane;
            int b  = gi / Nc;
            int n  = gi - b * Nc;
            kl = (b * Sc + __ldg(&idx[n])) & (KEYS - 1);
        }
        int k0 = __shfl_sync(0xffffffffu, kl, 0);
        int k1 = __shfl_sync(0xffffffffu, kl, 1);
        int k2 = __shfl_sync(0xffffffffu, kl, 2);
        int k3 = __shfl_sync(0xffffffffu, kl, 3);

        if ((k0 == k1) & (k1 == k2) & (k2 == k3)) {
            if (k0 != curKey) {
                if (curKey >= 0) flush_key(curKey, s, s2, lane);
                curKey = k0;
            }
            const float4* base = x4 + (size_t)g * C4;
            float4 v0 = __ldg(base + lane);
            float4 v1 = __ldg(base + lane + 32);
            float4 v2 = __ldg(base + lane + 64);
            s += (v0.x + v0.y) + (v0.z + v0.w)
               + (v1.x + v1.y) + (v1.z + v1.w)
               + (v2.x + v2.y) + (v2.z + v2.w);
            s2 = fmaf(v0.x, v0.x, s2); s2 = fmaf(v0.y, v0.y, s2);
            s2 = fmaf(v0.z, v0.z, s2); s2 = fmaf(v0.w, v0.w, s2);
            s2 = fmaf(v1.x, v1.x, s2); s2 = fmaf(v1.y, v1.y, s2);
            s2 = fmaf(v1.z, v1.z, s2); s2 = fmaf(v1.w, v1.w, s2);
            s2 = fmaf(v2.x, v2.x, s2); s2 = fmaf(v2.y, v2.y, s2);
            s2 = fmaf(v2.z, v2.z, s2); s2 = fmaf(v2.w, v2.w, s2);
        } else {
            // Rare: segment boundary inside the group. Per-point, 24 lanes.
            int ks[4] = {k0, k1, k2, k3};
            #pragma unroll
            for (int j = 0; j < 4; ++j) {
                if (ks[j] != curKey) {
                    if (curKey >= 0) flush_key(curKey, s, s2, lane);
                    curKey = ks[j];
                }
                if (lane < C4) {
                    float4 v = __ldg(x4 + (size_t)(g + j) * C4 + lane);
                    s += (v.x + v.y) + (v.z + v.w);
                    s2 = fmaf(v.x, v.x, s2); s2 = fmaf(v.y, v.y, s2);
                    s2 = fmaf(v.z, v.z, s2); s2 = fmaf(v.w, v.w, s2);
                }
            }
        }
    }
    if (curKey >= 0) flush_key(curKey, s, s2, lane);
}

// Per-(key, c4) scale/shift tables: o = x * sc + sh.
__global__ void pln_finalize_kernel(const int* __restrict__ offs,
                                    const float4* __restrict__ w4,
                                    const float4* __restrict__ b4)
{
    int i = blockIdx.x * blockDim.x + threadIdx.x;
    if (i < KEYS * C4) {
        int k  = i / C4;
        int c4 = i - k * C4;
        int seg = k & (Sc - 1);
        float cnt = (float)(offs[seg + 1] - offs[seg]) * (float)Cc;
        float m   = g_sum[k] / cnt;
        float var = g_sumsq[k] / cnt - m * m;
        float iv  = rsqrtf(var + EPSF);
        float4 wv = __ldg(w4 + c4);
        float4 bv = __ldg(b4 + c4);
        float4 sc, sh;
        sc.x = iv * wv.x; sh.x = fmaf(-m, sc.x, bv.x);
        sc.y = iv * wv.y; sh.y = fmaf(-m, sc.y, bv.y);
        sc.z = iv * wv.z; sh.z = fmaf(-m, sc.z, bv.z);
        sc.w = iv * wv.w; sh.w = fmaf(-m, sc.w, bv.w);
        g_sc[i] = sc;
        g_sh[i] = sh;
    }
}

// Division-free: total threads T is a multiple of C4, so each thread's c4 is
// loop-invariant and its point index advances by dp = T/C4 per iteration.
__global__ __launch_bounds__(256) void pln_norm_kernel(
    const float4* __restrict__ x4, const int* __restrict__ idx,
    float4* __restrict__ out4)
{
    const int P = Bc * Nc;
    const int E = P * C4;                      // 19,200,000 float4s
    int T   = gridDim.x * blockDim.x;          // multiple of 24 by launch config
    int tid = blockIdx.x * blockDim.x + threadIdx.x;
    int dp  = T / C4;

    int p  = tid / C4;
    int c4 = tid - p * C4;
    int b  = p / Nc;
    int n  = p - b * Nc;

    for (int e = tid; e < E; e += T) {
        int key = (b * Sc + __ldg(&idx[n])) & (KEYS - 1);
        int t   = key * C4 + c4;
        float4 sc = g_sc[t];
        float4 sh = g_sh[t];
        float4 xv = __ldg(x4 + e);
        float4 o;
        o.x = fmaf(xv.x, sc.x, sh.x);
        o.y = fmaf(xv.y, sc.y, sh.y);
        o.z = fmaf(xv.z, sc.z, sh.z);
        o.w = fmaf(xv.w, sc.w, sh.w);
        out4[e] = o;
        n += dp;
        if (n >= Nc) { n -= Nc; ++b; }
    }
}

extern "C" void kernel_launch(void* const* d_in, const int* in_sizes, int n_in,
                              void* d_out, int out_size) {
    const float4* x4   = (const float4*)d_in[0];
    const int*    offs = (const int*)d_in[1];
    const int*    idx  = (const int*)d_in[2];
    const float4* w4   = (const float4*)d_in[3];
    const float4* b4   = (const float4*)d_in[4];
    float4* out4 = (float4*)d_out;

    pln_zero_kernel<<<1, 128>>>();
    pln_reduce_kernel<<<2048, 256>>>(x4, idx);
    pln_finalize_kernel<<<12, 256>>>(offs, w4, b4);
    // grid*256 must be divisible by 24 -> grid divisible by 3.
    pln_norm_kernel<<<1185, 256>>>(x4, idx, out4);
}